// round 1
// baseline (speedup 1.0000x reference)
#include <cuda_runtime.h>
#include <math.h>

#define T_LEN 2048
#define B_SZ  64
#define CIN   64
#define HID   128
#define G4    512   // 4*HID gate rows
#define TT    64    // t-tile for gx kernel

#define REGK  96    // w_hh columns held in registers per gate-row thread
#define SMEMK 32    // remaining columns in shared memory
#define LSTM_SMEM ((SMEMK*G4 + 2*HID + G4)*4)

// Scratch (static __device__ — no allocation allowed)
__device__ float g_gx [(size_t)B_SZ * T_LEN * G4];   // [b][t][g], 256 MiB
__device__ float g_WcT[CIN * G4];                    // [k][g] = (w_ih @ pw_w)^T
__device__ float g_bc [G4];                          // w_ih@pw_b + b_ih + b_hh

// ---------------------------------------------------------------------------
// Stage 0: fold pointwise conv into the LSTM input projection.
//   Wc[g][k] = sum_o w_ih[g][o] * pw_w[o][k]   (stored transposed [k][g])
//   bc[g]    = sum_o w_ih[g][o] * pw_b[o] + b_ih[g] + b_hh[g]
// ---------------------------------------------------------------------------
__global__ void prep_kernel(const float* __restrict__ pw_w,
                            const float* __restrict__ pw_b,
                            const float* __restrict__ w_ih,
                            const float* __restrict__ b_ih,
                            const float* __restrict__ b_hh)
{
    int g = threadIdx.x;          // 0..511
    int k = blockIdx.x;           // 0..64 (64 == bias block)
    if (k < CIN) {
        float s = 0.f;
        #pragma unroll 8
        for (int o = 0; o < HID; ++o)
            s = fmaf(w_ih[g*HID + o], pw_w[o*CIN + k], s);
        g_WcT[k*G4 + g] = s;
    } else {
        float s = b_ih[g] + b_hh[g];
        #pragma unroll 8
        for (int o = 0; o < HID; ++o)
            s = fmaf(w_ih[g*HID + o], pw_b[o], s);
        g_bc[g] = s;
    }
}

// ---------------------------------------------------------------------------
// Stage 1: u = relu(BN(dwconv(x))) + x  fused with  gx = Wc @ u + bc
// One CTA per (batch, 64-wide t-tile). 512 threads: thread == gate row g.
// ---------------------------------------------------------------------------
__global__ __launch_bounds__(512, 1)
void gx_kernel(const float* __restrict__ x,
               const float* __restrict__ dw_w, const float* __restrict__ dw_b,
               const float* __restrict__ bn_g, const float* __restrict__ bn_b,
               const float* __restrict__ bn_m, const float* __restrict__ bn_v)
{
    __shared__ float xs[CIN * 68];    // halo tile [c][66] (stride 68)
    __shared__ float us[CIN * TT];    // u tile [c][64]
    __shared__ float ca[CIN], cd[CIN], cw0[CIN], cw1[CIN], cw2[CIN];

    const int tid = threadIdx.x;
    const int b   = blockIdx.y;
    const int t0  = blockIdx.x * TT;

    if (tid < CIN) {
        int c = tid;
        float inv = bn_g[c] * rsqrtf(bn_v[c] + 1e-5f);
        ca[c]  = inv;
        cd[c]  = (dw_b[c] - bn_m[c]) * inv + bn_b[c];
        cw0[c] = dw_w[c*3 + 0];
        cw1[c] = dw_w[c*3 + 1];
        cw2[c] = dw_w[c*3 + 2];
    }
    // load x halo [t0-1, t0+64]
    for (int idx = tid; idx < CIN * 66; idx += 512) {
        int c = idx / 66, i = idx % 66;
        int t = t0 - 1 + i;
        xs[c*68 + i] = (t >= 0 && t < T_LEN) ? x[((size_t)b*CIN + c)*T_LEN + t] : 0.f;
    }
    __syncthreads();

    // depthwise conv + BN + relu + residual
    for (int idx = tid; idx < CIN * TT; idx += 512) {
        int c = idx >> 6, tt = idx & 63;
        const float* xr = xs + c*68 + tt;
        float conv = fmaf(cw0[c], xr[0], fmaf(cw1[c], xr[1], cw2[c]*xr[2]));
        float v = fmaf(conv, ca[c], cd[c]);
        us[c*TT + tt] = fmaxf(v, 0.f) + xr[1];
    }
    __syncthreads();

    // gx[g][t] = sum_k Wc[g][k] * u[k][t] + bc[g]
    const int g = tid;
    float acc[TT];
    {
        float bcv = g_bc[g];
        #pragma unroll
        for (int t = 0; t < TT; ++t) acc[t] = bcv;
    }
    #pragma unroll 4
    for (int k = 0; k < CIN; ++k) {
        float w = g_WcT[k*G4 + g];                       // coalesced, L2-hot
        const float4* u4 = (const float4*)(us + (k << 6)); // warp-broadcast
        #pragma unroll
        for (int q = 0; q < TT/4; ++q) {
            float4 uv = u4[q];
            acc[4*q+0] = fmaf(w, uv.x, acc[4*q+0]);
            acc[4*q+1] = fmaf(w, uv.y, acc[4*q+1]);
            acc[4*q+2] = fmaf(w, uv.z, acc[4*q+2]);
            acc[4*q+3] = fmaf(w, uv.w, acc[4*q+3]);
        }
    }
    float* outp = g_gx + ((size_t)(b*T_LEN + t0)) * G4 + g;
    #pragma unroll
    for (int t = 0; t < TT; ++t) outp[(size_t)t * G4] = acc[t];   // coalesced in g
}

// ---------------------------------------------------------------------------
// Stage 2: LSTM recurrence. One persistent CTA per batch row, 512 threads.
// Thread g owns gate-row g of w_hh: REGK cols in registers, SMEMK cols in smem.
// ---------------------------------------------------------------------------
__device__ __forceinline__ float sigmoid_f(float v) {
    return 1.f / (1.f + __expf(-v));
}
__device__ __forceinline__ float tanh_f(float v) {
    float e = __expf(2.f * v);
    return 1.f - 2.f / (e + 1.f);   // safe at +-inf
}

__global__ __launch_bounds__(512, 1)
void lstm_kernel(const float* __restrict__ w_hh, float* __restrict__ out)
{
    extern __shared__ float sm[];
    float* ws    = sm;                 // [SMEMK][512] conflict-free by g
    float* hbuf  = sm + SMEMK*G4;      // [2][128] double buffer
    float* gates = hbuf + 2*HID;       // [512]

    const int g = threadIdx.x;
    const int b = blockIdx.x;

    // register-resident slice of w_hh row g (cols 0..REGK-1)
    float wreg[REGK];
    {
        const float4* wp = (const float4*)(w_hh + (size_t)g * HID);
        #pragma unroll
        for (int q = 0; q < REGK/4; ++q) {
            float4 v = wp[q];
            wreg[4*q+0] = v.x; wreg[4*q+1] = v.y;
            wreg[4*q+2] = v.z; wreg[4*q+3] = v.w;
        }
    }
    // smem slice (cols REGK..127), layout [k][g]
    #pragma unroll
    for (int i = 0; i < SMEMK; ++i)
        ws[i*G4 + g] = w_hh[(size_t)g*HID + REGK + i];
    if (g < 2*HID) hbuf[g] = 0.f;

    float c_state = 0.f;
    const float* gxp = g_gx + (size_t)b * T_LEN * G4 + g;
    float gx_next = gxp[0];
    float* outb = out + (size_t)b * HID * T_LEN;
    __syncthreads();

    int p = 0;
    for (int t = 0; t < T_LEN; ++t) {
        float acc = gx_next;
        if (t + 1 < T_LEN) gx_next = gxp[(size_t)(t+1) * G4];  // prefetch

        const float4* h4 = (const float4*)(hbuf + p*HID);
        #pragma unroll
        for (int q = 0; q < REGK/4; ++q) {
            float4 hv = h4[q];                      // warp-broadcast LDS.128
            acc = fmaf(wreg[4*q+0], hv.x, acc);
            acc = fmaf(wreg[4*q+1], hv.y, acc);
            acc = fmaf(wreg[4*q+2], hv.z, acc);
            acc = fmaf(wreg[4*q+3], hv.w, acc);
        }
        #pragma unroll
        for (int q = 0; q < SMEMK/4; ++q) {
            float4 hv = h4[REGK/4 + q];
            acc = fmaf(ws[(4*q+0)*G4 + g], hv.x, acc);
            acc = fmaf(ws[(4*q+1)*G4 + g], hv.y, acc);
            acc = fmaf(ws[(4*q+2)*G4 + g], hv.z, acc);
            acc = fmaf(ws[(4*q+3)*G4 + g], hv.w, acc);
        }
        gates[g] = acc;
        __syncthreads();

        if (g < HID) {
            float iv = sigmoid_f(gates[g]);
            float fv = sigmoid_f(gates[g + 128]);
            float gv = tanh_f  (gates[g + 256]);
            float ov = sigmoid_f(gates[g + 384]);
            c_state = fmaf(fv, c_state, iv * gv);
            float h = ov * tanh_f(c_state);
            hbuf[(p ^ 1)*HID + g] = h;
            outb[(size_t)g * T_LEN + t] = h;
        }
        __syncthreads();
        p ^= 1;
    }
}

// ---------------------------------------------------------------------------
extern "C" void kernel_launch(void* const* d_in, const int* in_sizes, int n_in,
                              void* d_out, int out_size)
{
    (void)in_sizes; (void)n_in; (void)out_size;
    const float* x     = (const float*)d_in[0];
    const float* dw_w  = (const float*)d_in[1];
    const float* dw_b  = (const float*)d_in[2];
    const float* bn_g  = (const float*)d_in[3];
    const float* bn_b  = (const float*)d_in[4];
    const float* bn_m  = (const float*)d_in[5];
    const float* bn_v  = (const float*)d_in[6];
    const float* pw_w  = (const float*)d_in[7];
    const float* pw_b  = (const float*)d_in[8];
    const float* w_ih  = (const float*)d_in[9];
    const float* w_hh  = (const float*)d_in[10];
    const float* b_ih  = (const float*)d_in[11];
    const float* b_hh  = (const float*)d_in[12];
    float* out = (float*)d_out;

    cudaFuncSetAttribute(lstm_kernel,
                         cudaFuncAttributeMaxDynamicSharedMemorySize, LSTM_SMEM);

    prep_kernel<<<65, 512>>>(pw_w, pw_b, w_ih, b_ih, b_hh);
    gx_kernel<<<dim3(T_LEN/TT, B_SZ), 512>>>(x, dw_w, dw_b, bn_g, bn_b, bn_m, bn_v);
    lstm_kernel<<<B_SZ, 512, LSTM_SMEM>>>(w_hh, out);
}

// round 3
// speedup vs baseline: 1.4485x; 1.4485x over previous
#include <cuda_runtime.h>
#include <math.h>

#define T_LEN 2048
#define B_SZ  64
#define CIN   64
#define HID   128
#define G4    512
#define TT    64

#define NT    256          // lstm threads (2 gate rows per thread)
#define REGK  96           // w_hh columns register-resident per row
#define SMEMK 32           // remaining columns in shared memory
#define LSTM_SMEM ((SMEMK*G4 + 2*HID + G4)*4)

// packed fp32x2 helpers (sm_103a). "f" = .f32 reg, "l" = .b64 reg.
#define FMA2(d, a, b, c) \
    asm("fma.rn.f32x2 %0, %1, %2, %3;" : "=l"(d) : "l"(a), "l"(b), "l"(c))
#define PACK2(out, lo, hi) \
    asm("mov.b64 %0, {%1, %2};" : "=l"(out) : "f"(lo), "f"(hi))
#define UNPACK2(lo, hi, in) \
    asm("mov.b64 {%0, %1}, %2;" : "=f"(lo), "=f"(hi) : "l"(in))

__device__ float g_gx [(size_t)B_SZ * T_LEN * G4];   // [b][t][g]
__device__ float g_WcT[CIN * G4];                    // [k][g]
__device__ float g_bc [G4];

// ---------------------------------------------------------------------------
// Stage 0: fold pointwise conv into LSTM input projection
// ---------------------------------------------------------------------------
__global__ void prep_kernel(const float* __restrict__ pw_w,
                            const float* __restrict__ pw_b,
                            const float* __restrict__ w_ih,
                            const float* __restrict__ b_ih,
                            const float* __restrict__ b_hh)
{
    int g = threadIdx.x;
    int k = blockIdx.x;
    if (k < CIN) {
        float s = 0.f;
        #pragma unroll 8
        for (int o = 0; o < HID; ++o)
            s = fmaf(w_ih[g*HID + o], pw_w[o*CIN + k], s);
        g_WcT[k*G4 + g] = s;
    } else {
        float s = b_ih[g] + b_hh[g];
        #pragma unroll 8
        for (int o = 0; o < HID; ++o)
            s = fmaf(w_ih[g*HID + o], pw_b[o], s);
        g_bc[g] = s;
    }
}

// ---------------------------------------------------------------------------
// Stage 1: u = relu(BN(dwconv(x))) + x  fused with  gx = Wc @ u + bc
// f32x2 over t-pairs.
// ---------------------------------------------------------------------------
__global__ __launch_bounds__(512, 1)
void gx_kernel(const float* __restrict__ x,
               const float* __restrict__ dw_w, const float* __restrict__ dw_b,
               const float* __restrict__ bn_g, const float* __restrict__ bn_b,
               const float* __restrict__ bn_m, const float* __restrict__ bn_v)
{
    __shared__ __align__(16) float us[CIN * TT];   // u tile [c][64]
    __shared__ __align__(16) float xs[CIN * 68];   // halo tile [c][66]
    __shared__ float ca[CIN], cd[CIN], cw0[CIN], cw1[CIN], cw2[CIN];

    const int tid = threadIdx.x;
    const int b   = blockIdx.y;
    const int t0  = blockIdx.x * TT;

    if (tid < CIN) {
        int c = tid;
        float inv = bn_g[c] * rsqrtf(bn_v[c] + 1e-5f);
        ca[c]  = inv;
        cd[c]  = (dw_b[c] - bn_m[c]) * inv + bn_b[c];
        cw0[c] = dw_w[c*3 + 0];
        cw1[c] = dw_w[c*3 + 1];
        cw2[c] = dw_w[c*3 + 2];
    }
    for (int idx = tid; idx < CIN * 66; idx += 512) {
        int c = idx / 66, i = idx % 66;
        int t = t0 - 1 + i;
        xs[c*68 + i] = (t >= 0 && t < T_LEN) ? x[((size_t)b*CIN + c)*T_LEN + t] : 0.f;
    }
    __syncthreads();

    for (int idx = tid; idx < CIN * TT; idx += 512) {
        int c = idx >> 6, tt = idx & 63;
        const float* xr = xs + c*68 + tt;
        float conv = fmaf(cw0[c], xr[0], fmaf(cw1[c], xr[1], cw2[c]*xr[2]));
        float v = fmaf(conv, ca[c], cd[c]);
        us[c*TT + tt] = fmaxf(v, 0.f) + xr[1];
    }
    __syncthreads();

    const int g = tid;
    unsigned long long acc2[TT/2];
    {
        float bcv = g_bc[g];
        unsigned long long bp; PACK2(bp, bcv, bcv);
        #pragma unroll
        for (int q = 0; q < TT/2; ++q) acc2[q] = bp;
    }
    #pragma unroll 4
    for (int k = 0; k < CIN; ++k) {
        float w = g_WcT[k*G4 + g];
        unsigned long long wp; PACK2(wp, w, w);
        const ulonglong2* u2 = (const ulonglong2*)(us + (k << 6));
        #pragma unroll
        for (int q = 0; q < TT/4; ++q) {
            ulonglong2 uv = u2[q];
            FMA2(acc2[2*q+0], wp, uv.x, acc2[2*q+0]);
            FMA2(acc2[2*q+1], wp, uv.y, acc2[2*q+1]);
        }
    }
    float* outp = g_gx + ((size_t)(b*T_LEN + t0)) * G4 + g;
    #pragma unroll
    for (int q = 0; q < TT/2; ++q) {
        float lo, hi; UNPACK2(lo, hi, acc2[q]);
        outp[(size_t)(2*q+0) * G4] = lo;
        outp[(size_t)(2*q+1) * G4] = hi;
    }
}

// ---------------------------------------------------------------------------
// Stage 2: LSTM recurrence. 64 CTAs x 256 threads; thread t owns gate rows
// t and t+256. 96 cols/row in registers (f32x2), 32 cols/row in smem (scalar).
// ---------------------------------------------------------------------------
__device__ __forceinline__ float sigmoid_f(float v) {
    return __fdividef(1.f, 1.f + __expf(-v));
}
__device__ __forceinline__ float tanh_f(float v) {
    return 1.f - __fdividef(2.f, __expf(2.f * v) + 1.f);
}

__global__ __launch_bounds__(NT, 1)
void lstm_kernel(const float* __restrict__ w_hh, float* __restrict__ out)
{
    extern __shared__ __align__(16) float sm[];
    float* ws    = sm;                 // [SMEMK][512]
    float* hbuf  = sm + SMEMK*G4;      // [2][128]
    float* gates = hbuf + 2*HID;       // [512]

    const int t  = threadIdx.x;
    const int b  = blockIdx.x;
    const int r0 = t;
    const int r1 = t + 256;

    // register-resident weight pairs for both rows (cols 0..REGK-1)
    unsigned long long wA[REGK/2], wB[REGK/2];
    {
        const ulonglong2* pA = (const ulonglong2*)(w_hh + (size_t)r0 * HID);
        const ulonglong2* pB = (const ulonglong2*)(w_hh + (size_t)r1 * HID);
        #pragma unroll
        for (int q = 0; q < REGK/4; ++q) {
            ulonglong2 vA = pA[q]; wA[2*q] = vA.x; wA[2*q+1] = vA.y;
            ulonglong2 vB = pB[q]; wB[2*q] = vB.x; wB[2*q+1] = vB.y;
        }
    }
    // smem slice (cols REGK..127), layout [k][row]
    #pragma unroll
    for (int i = 0; i < SMEMK; ++i) {
        ws[i*G4 + r0] = w_hh[(size_t)r0*HID + REGK + i];
        ws[i*G4 + r1] = w_hh[(size_t)r1*HID + REGK + i];
    }
    hbuf[t] = 0.f;    // covers both 128-wide buffers (NT == 256)

    float c_state = 0.f;
    const float* gxA = g_gx + (size_t)b * T_LEN * G4 + r0;
    const float* gxB = gxA + 256;
    float gxA_n = gxA[0], gxB_n = gxB[0];
    float* outb = out + (size_t)b * HID * T_LEN;
    float ob[4];
    __syncthreads();

    int p = 0;
    for (int step = 0; step < T_LEN; ++step) {
        float accA = gxA_n, accB = gxB_n;
        if (step + 1 < T_LEN) {
            gxA_n = gxA[(size_t)(step+1) * G4];
            gxB_n = gxB[(size_t)(step+1) * G4];
        }

        unsigned long long a2, b2;
        PACK2(a2, 0.f, 0.f);
        b2 = a2;

        const ulonglong2* h2 = (const ulonglong2*)(hbuf + p*HID);
        #pragma unroll
        for (int q = 0; q < REGK/4; ++q) {            // cols 0..95 packed
            ulonglong2 hv = h2[q];
            FMA2(a2, wA[2*q+0], hv.x, a2);
            FMA2(a2, wA[2*q+1], hv.y, a2);
            FMA2(b2, wB[2*q+0], hv.x, b2);
            FMA2(b2, wB[2*q+1], hv.y, b2);
        }
        const float4* h4 = (const float4*)(hbuf + p*HID);
        #pragma unroll
        for (int j = 0; j < SMEMK/4; ++j) {           // cols 96..127 scalar
            float4 hv = h4[REGK/4 + j];
            accA = fmaf(ws[(4*j+0)*G4 + r0], hv.x, accA);
            accA = fmaf(ws[(4*j+1)*G4 + r0], hv.y, accA);
            accA = fmaf(ws[(4*j+2)*G4 + r0], hv.z, accA);
            accA = fmaf(ws[(4*j+3)*G4 + r0], hv.w, accA);
            accB = fmaf(ws[(4*j+0)*G4 + r1], hv.x, accB);
            accB = fmaf(ws[(4*j+1)*G4 + r1], hv.y, accB);
            accB = fmaf(ws[(4*j+2)*G4 + r1], hv.z, accB);
            accB = fmaf(ws[(4*j+3)*G4 + r1], hv.w, accB);
        }
        {
            float lo, hi;
            UNPACK2(lo, hi, a2); gates[r0] = accA + lo + hi;
            UNPACK2(lo, hi, b2); gates[r1] = accB + lo + hi;
        }

        if (t < 128) {
            asm volatile("bar.sync 1, %0;" :: "n"(NT) : "memory");
            float iv = sigmoid_f(gates[t]);
            float fv = sigmoid_f(gates[t + 128]);
            float gv = tanh_f  (gates[t + 256]);
            float ov = sigmoid_f(gates[t + 384]);
            c_state = fmaf(fv, c_state, iv * gv);
            float h = ov * tanh_f(c_state);
            hbuf[(p ^ 1)*HID + t] = h;
            ob[step & 3] = h;
            if ((step & 3) == 3)
                *(float4*)(outb + (size_t)t * T_LEN + (step - 3)) =
                    make_float4(ob[0], ob[1], ob[2], ob[3]);
        } else {
            asm volatile("bar.arrive 1, %0;" :: "n"(NT) : "memory");
        }
        __syncthreads();
        p ^= 1;
    }
}

// ---------------------------------------------------------------------------
extern "C" void kernel_launch(void* const* d_in, const int* in_sizes, int n_in,
                              void* d_out, int out_size)
{
    (void)in_sizes; (void)n_in; (void)out_size;
    const float* x     = (const float*)d_in[0];
    const float* dw_w  = (const float*)d_in[1];
    const float* dw_b  = (const float*)d_in[2];
    const float* bn_g  = (const float*)d_in[3];
    const float* bn_b  = (const float*)d_in[4];
    const float* bn_m  = (const float*)d_in[5];
    const float* bn_v  = (const float*)d_in[6];
    const float* pw_w  = (const float*)d_in[7];
    const float* pw_b  = (const float*)d_in[8];
    const float* w_ih  = (const float*)d_in[9];
    const float* w_hh  = (const float*)d_in[10];
    const float* b_ih  = (const float*)d_in[11];
    const float* b_hh  = (const float*)d_in[12];
    float* out = (float*)d_out;

    cudaFuncSetAttribute(lstm_kernel,
                         cudaFuncAttributeMaxDynamicSharedMemorySize, LSTM_SMEM);

    prep_kernel<<<65, 512>>>(pw_w, pw_b, w_ih, b_ih, b_hh);
    gx_kernel<<<dim3(T_LEN/TT, B_SZ), 512>>>(x, dw_w, dw_b, bn_g, bn_b, bn_m, bn_v);
    lstm_kernel<<<B_SZ, NT, LSTM_SMEM>>>(w_hh, out);
}